// round 16
// baseline (speedup 1.0000x reference)
#include <cuda_runtime.h>
#include <cuda_fp16.h>
#include <stdint.h>
#include <math.h>

#define B_ 4
#define L_ 2048
#define D_ 1024
#define NBL (B_ * L_)
#define WIN 256                         // decay truncation window (γ^257 ≈ 2.9e-4 rel)

#define LOG2G  (-0.045803734f)          // log2(0.96875)
#define L2_1E4 (13.287712379549449f)    // log2(10000)

#define STG_BYTES 36864                 // 128-row stage: A(18432) + B(18432)
#define GEMM_SMEM (2 * STG_BYTES)       // 72 KB
#define AV_STG 27648                    // 64-row stage: A(9216) + B(18432)
#define AV_SMEM (2 * AV_STG)            // 54 KB

// ------------------- global scratch (allocation-free rule) -------------------
__device__ __align__(16) __half g_X16[NBL * D_];
__device__ __align__(16) __half g_W16[3][D_ * D_];        // transposed [n][k]
__device__ __align__(16) __half g_Q16[NBL * D_];
__device__ __align__(16) __half g_K16[NBL * D_];
__device__ __align__(16) __half g_T16[NBL * D_];          // V^T [d][l]
__device__ __align__(16) __half g_A[(size_t)B_ * L_ * L_];
__device__ __align__(16) float2 g_xtQ[(size_t)L_ * (D_ / 2)];  // cQ,sQ
__device__ __align__(16) float2 g_xtK[(size_t)L_ * (D_ / 2)];  // cK,sK

// ------------------------------- helpers -------------------------------------
__device__ __forceinline__ uint32_t smem_u32(const void* p) {
    uint32_t a;
    asm("{ .reg .u64 t; cvta.to.shared.u64 t, %1; cvt.u32.u64 %0, t; }"
        : "=r"(a) : "l"(p));
    return a;
}

__device__ __forceinline__ void ldm4(uint32_t* r, uint32_t a) {
    asm volatile("ldmatrix.sync.aligned.m8n8.x4.shared.b16 {%0,%1,%2,%3}, [%4];"
                 : "=r"(r[0]), "=r"(r[1]), "=r"(r[2]), "=r"(r[3]) : "r"(a));
}

__device__ __forceinline__ void mma_f16(float* c, const uint32_t* a, const uint32_t* b) {
    asm volatile(
        "mma.sync.aligned.m16n8k16.row.col.f32.f16.f16.f32 "
        "{%0,%1,%2,%3}, {%4,%5,%6,%7}, {%8,%9}, {%0,%1,%2,%3};"
        : "+f"(c[0]), "+f"(c[1]), "+f"(c[2]), "+f"(c[3])
        : "r"(a[0]), "r"(a[1]), "r"(a[2]), "r"(a[3]), "r"(b[0]), "r"(b[1]));
}

// fp16-accumulate MMA with C=0, drained immediately into fp32 masters.
// One fp16 rounding of the K=16 partial per call (~2.8e-4 rel contribution).
__device__ __forceinline__ void mma_f16h(float* c, const uint32_t* a, const uint32_t* b) {
    uint32_t d0, d1;
    asm volatile(
        "mma.sync.aligned.m16n8k16.row.col.f16.f16.f16.f16 "
        "{%0,%1}, {%2,%3,%4,%5}, {%6,%7}, {%8,%8};"
        : "=r"(d0), "=r"(d1)
        : "r"(a[0]), "r"(a[1]), "r"(a[2]), "r"(a[3]), "r"(b[0]), "r"(b[1]), "r"(0u));
    __half2 h0 = *reinterpret_cast<__half2*>(&d0);
    __half2 h1 = *reinterpret_cast<__half2*>(&d1);
    float2 f0 = __half22float2(h0);
    float2 f1 = __half22float2(h1);
    c[0] += f0.x; c[1] += f0.y; c[2] += f1.x; c[3] += f1.y;
}

__device__ __forceinline__ void cp16(uint32_t dst, const void* src) {
    asm volatile("cp.async.cg.shared.global [%0], [%1], 16;" :: "r"(dst), "l"(src));
}
__device__ __forceinline__ void cp_commit() {
    asm volatile("cp.async.commit_group;" ::: "memory");
}
template <int N>
__device__ __forceinline__ void cp_wait() {
    asm volatile("cp.async.wait_group %0;" :: "n"(N) : "memory");
}

// async-copy ROWS x 64 cols (16-bit), gmem(stride ld) -> smem(stride 72)
template <int ROWS>
__device__ __forceinline__ void cpaR(uint32_t sb, const uint16_t* __restrict__ g,
                                     int ld, int t) {
#pragma unroll
    for (int it = 0; it < ROWS / 32; ++it) {
        int idx = t + it * 256;
        int r = idx >> 3, sg = (idx & 7) << 3;
        cp16(sb + (uint32_t)(r * 72 + sg) * 2, g + (size_t)r * ld + sg);
    }
}

// -- CTA 128x128 GEMM mainloop: fp16, K-chunk 64, 2-stage cp.async (R10 form) -
// H16: use fp16-accumulate MMA (immediate drain) instead of fp32-accumulate.
template <bool H16>
__device__ __forceinline__ void gemm_loop1(
    float acc[2][8][4],
    const __half* __restrict__ Ag, const __half* __restrict__ Bg,
    int lda, int ldb, int nch64, uint32_t smb, int t) {
    const int lane = t & 31, w = t >> 5;
    const int wm0 = (w >> 1) << 5;
    const int wn0 = (w & 1) << 6;

    const int arow = wm0 + (lane & 15);
    const int acol = (lane >> 4) << 3;
    const uint32_t aOff = (uint32_t)(arow * 72 + acol) * 2;
    const int brow = wn0 + ((lane >> 4) << 3) + (lane & 7);
    const int bcol = ((lane >> 3) & 1) << 3;
    const uint32_t bOff = 18432u + (uint32_t)(brow * 72 + bcol) * 2;

    const uint16_t* Au = (const uint16_t*)Ag;
    const uint16_t* Bu = (const uint16_t*)Bg;

    cpaR<128>(smb, Au, lda, t);
    cpaR<128>(smb + 18432, Bu, ldb, t);
    cp_commit();

    for (int ch = 0; ch < nch64; ++ch) {
        if (ch + 1 < nch64) {
            uint32_t ns = smb + ((ch + 1) & 1) * STG_BYTES;
            cpaR<128>(ns, Au + (ch + 1) * 64, lda, t);
            cpaR<128>(ns + 18432, Bu + (ch + 1) * 64, ldb, t);
            cp_commit();
            cp_wait<1>();
        } else {
            cp_wait<0>();
        }
        __syncthreads();

        const uint32_t sb = smb + (ch & 1) * STG_BYTES;
        const uint32_t aA = sb + aOff;
        const uint32_t bB = sb + bOff;

#pragma unroll
        for (int kk = 0; kk < 4; ++kk) {
            const uint32_t kb = kk * 32;
            uint32_t af[2][4], bf[8][2];
#pragma unroll
            for (int i = 0; i < 2; ++i)
                ldm4(af[i], aA + i * 16 * 144 + kb);
#pragma unroll
            for (int jp = 0; jp < 4; ++jp) {
                uint32_t tp[4];
                ldm4(tp, bB + jp * 16 * 144 + kb);
                bf[2 * jp][0] = tp[0];     bf[2 * jp][1] = tp[1];
                bf[2 * jp + 1][0] = tp[2]; bf[2 * jp + 1][1] = tp[3];
            }
#pragma unroll
            for (int i = 0; i < 2; ++i)
#pragma unroll
                for (int j = 0; j < 8; ++j) {
                    if (H16) mma_f16h(acc[i][j], af[i], bf[j]);
                    else     mma_f16(acc[i][j], af[i], bf[j]);
                }
        }
        __syncthreads();
    }
}

// ---- CTA 64x128 GEMM mainloop (av): warp layout 2x4, acc[2][4][4] ----------
__device__ __forceinline__ void gemm_loop64(
    float acc[2][4][4],
    const __half* __restrict__ Ag, const __half* __restrict__ Bg,
    int lda, int ldb, int nch64, uint32_t smb, int t) {
    const int lane = t & 31, w = t >> 5;
    const int wm0 = (w >> 2) << 5;   // 0,32
    const int wn0 = (w & 3) << 5;    // 0,32,64,96

    const int arow = wm0 + (lane & 15);
    const int acol = (lane >> 4) << 3;
    const uint32_t aOff = (uint32_t)(arow * 72 + acol) * 2;
    const int brow = wn0 + ((lane >> 4) << 3) + (lane & 7);
    const int bcol = ((lane >> 3) & 1) << 3;
    const uint32_t bOff = 9216u + (uint32_t)(brow * 72 + bcol) * 2;

    const uint16_t* Au = (const uint16_t*)Ag;
    const uint16_t* Bu = (const uint16_t*)Bg;

    cpaR<64>(smb, Au, lda, t);
    cpaR<128>(smb + 9216, Bu, ldb, t);
    cp_commit();

    for (int ch = 0; ch < nch64; ++ch) {
        if (ch + 1 < nch64) {
            uint32_t ns = smb + ((ch + 1) & 1) * AV_STG;
            cpaR<64>(ns, Au + (ch + 1) * 64, lda, t);
            cpaR<128>(ns + 9216, Bu + (ch + 1) * 64, ldb, t);
            cp_commit();
            cp_wait<1>();
        } else {
            cp_wait<0>();
        }
        __syncthreads();

        const uint32_t sb = smb + (ch & 1) * AV_STG;
        const uint32_t aA = sb + aOff;
        const uint32_t bB = sb + bOff;

#pragma unroll
        for (int kk = 0; kk < 4; ++kk) {
            const uint32_t kb = kk * 32;
            uint32_t af[2][4], bf[4][2];
#pragma unroll
            for (int i = 0; i < 2; ++i)
                ldm4(af[i], aA + i * 16 * 144 + kb);
#pragma unroll
            for (int jp = 0; jp < 2; ++jp) {
                uint32_t tp[4];
                ldm4(tp, bB + jp * 16 * 144 + kb);
                bf[2 * jp][0] = tp[0];     bf[2 * jp][1] = tp[1];
                bf[2 * jp + 1][0] = tp[2]; bf[2 * jp + 1][1] = tp[3];
            }
#pragma unroll
            for (int i = 0; i < 2; ++i)
#pragma unroll
                for (int j = 0; j < 4; ++j)
                    mma_f16(acc[i][j], af[i], bf[j]);
        }
        __syncthreads();
    }
}

// -------------- fused prep: cvt X + xt tables + W transpose ------------------
#define NX_BLK ((NBL * D_) / 1024)      // 8192
#define XT_BLK ((L_ * 512) / 256)       // 4096
__global__ __launch_bounds__(256) void prep_kernel(const float* __restrict__ X,
                                                   const float* __restrict__ WQ,
                                                   const float* __restrict__ WK,
                                                   const float* __restrict__ WV) {
    __shared__ float ts[32][33];
    int bx = blockIdx.x;
    if (bx < NX_BLK) {
        size_t i = ((size_t)bx * 256 + threadIdx.x) * 4;
        float4 v = *reinterpret_cast<const float4*>(X + i);
        __half2 a = __floats2half2_rn(v.x, v.y);
        __half2 b = __floats2half2_rn(v.z, v.w);
        uint2 o;
        o.x = *reinterpret_cast<uint32_t*>(&a);
        o.y = *reinterpret_cast<uint32_t*>(&b);
        *reinterpret_cast<uint2*>(g_X16 + i) = o;
    } else if (bx < NX_BLK + XT_BLK) {
        int idx = (bx - NX_BLK) * 256 + threadIdx.x;  // pos*512 + cp
        int pos = idx >> 9;
        int cp = idx & 511;
        float sv = (2.0f * cp + 409.6f) * (1.0f / 1433.6f);
        float sc = exp2f((float)pos * (1.0f / 512.0f) * log2f(sv));
        float invf = exp2f(-(float)cp * (L2_1E4 / 512.0f));
        float s, c;
        sincosf((float)pos * invf, &s, &c);
        g_xtQ[idx] = make_float2(c * sc, s * sc);
        g_xtK[idx] = make_float2(c / sc, s / sc);
    } else {
        // W transpose: 3 x 1024 blocks, each 32x32
        int idx = bx - NX_BLK - XT_BLK;
        int S = idx >> 10;
        int rem = idx & 1023;
        int n0 = (rem & 31) * 32, k0 = (rem >> 5) * 32;
        const float* W = (S == 0) ? WQ : (S == 1 ? WK : WV);
        int tx = threadIdx.x & 31, ty = threadIdx.x >> 5;
#pragma unroll
        for (int j = 0; j < 4; ++j)
            ts[ty + 8 * j][tx] = W[(size_t)(k0 + ty + 8 * j) * D_ + n0 + tx];
        __syncthreads();
#pragma unroll
        for (int j = 0; j < 4; ++j)
            g_W16[S][(size_t)(n0 + ty + 8 * j) * D_ + k0 + tx] =
                __float2half_rn(ts[tx][ty + 8 * j]);
    }
}

// --------------- fused projection GEMM: z = 0:Q, 1:K, 2:V(->V^T) -------------
__global__ __launch_bounds__(256, 2) void proj_mm() {
    extern __shared__ uint16_t dsm[];
    uint32_t smb = smem_u32(dsm);
    float acc[2][8][4] = {};
    const int t = threadIdx.x;
    const int MODE = blockIdx.z;
    const int n0 = blockIdx.x << 7, m0 = blockIdx.y << 7;

    gemm_loop1<true>(acc,
                     g_X16 + (size_t)m0 * D_,
                     g_W16[MODE] + (size_t)n0 * D_,
                     D_, D_, D_ / 64, smb, t);

    const int lane = t & 31, w = t >> 5;
    const int wm0 = (w >> 1) << 5, wn0 = (w & 1) << 6;
    const int rf = lane >> 2, cf = (lane & 3) << 1;

    if (MODE == 2) {
        // ---- V: write transposed directly to g_T16[d][l] via smem staging ----
#pragma unroll
        for (int i = 0; i < 2; ++i)
#pragma unroll
            for (int hf = 0; hf < 2; ++hf) {
                int r = wm0 + i * 16 + rf + hf * 8;
#pragma unroll
                for (int j = 0; j < 8; ++j) {
                    int c = wn0 + j * 8 + cf;
                    dsm[(uint32_t)c * 136 + r] =
                        (uint16_t)__half_as_ushort(__float2half_rn(acc[i][j][hf * 2]));
                    dsm[(uint32_t)(c + 1) * 136 + r] =
                        (uint16_t)__half_as_ushort(__float2half_rn(acc[i][j][hf * 2 + 1]));
                }
            }
        __syncthreads();
        const int b = m0 >> 11;
        const int l0 = m0 & (L_ - 1);
        __half* T = g_T16 + (size_t)b * L_ * D_;
#pragma unroll
        for (int it = 0; it < 8; ++it) {
            int idx = t + it * 256;
            int c = idx >> 4;
            int sg = (idx & 15) << 3;
            float4 v = *reinterpret_cast<const float4*>(dsm + (uint32_t)c * 136 + sg);
            *reinterpret_cast<float4*>(T + (size_t)(n0 + c) * L_ + l0 + sg) = v;
        }
        return;
    }

    // ---- Q / K: xPos rotation epilogue ----
    __half* dst = (MODE == 0) ? g_Q16 : g_K16;
    const float2* xt = (MODE == 0) ? g_xtQ : g_xtK;
#pragma unroll
    for (int i = 0; i < 2; ++i)
#pragma unroll
        for (int hf = 0; hf < 2; ++hf) {
            int row = m0 + wm0 + i * 16 + rf + hf * 8;
            int pos = row & (L_ - 1);
#pragma unroll
            for (int j = 0; j < 8; ++j) {
                int col = n0 + wn0 + j * 8 + cf;
                float x0 = acc[i][j][hf * 2], x1 = acc[i][j][hf * 2 + 1];
                float2 tb = xt[(size_t)pos * 512 + (col >> 1)];
                float y0 = x0 * tb.x - x1 * tb.y;
                float y1 = x1 * tb.x + x0 * tb.y;
                __half2 hv = __floats2half2_rn(y0, y1);
                *reinterpret_cast<__half2*>(dst + (size_t)row * D_ + col) = hv;
            }
        }
}

// -------------------- A = (Q K^T) * decay, fp16 (window tiles only) ----------
__global__ __launch_bounds__(256) void qk_mm() {
    extern __shared__ uint16_t dsm[];
    uint32_t smb = smem_u32(dsm);
    __shared__ float pw[128], ipw[128];
    const int t = threadIdx.x;
    const int b = blockIdx.z;
    const int nt = blockIdx.y;                 // query tile
    const int mt = nt - 2 + (int)blockIdx.x;   // key tile within 256-window
    if (mt < 0) return;
    const int n0 = nt << 7, m0 = mt << 7;

    if (t < 128) {
        pw[t] = exp2f((float)t * LOG2G);
        ipw[t] = exp2f(-(float)t * LOG2G);
    }

    float acc[2][8][4] = {};
    gemm_loop1<false>(acc,
                      g_Q16 + (size_t)(b * L_ + n0) * D_,
                      g_K16 + (size_t)(b * L_ + m0) * D_,
                      D_, D_, D_ / 64, smb, t);

    const int lane = t & 31, w = t >> 5;
    const int wm0 = (w >> 1) << 5, wn0 = (w & 1) << 6;
    const int rf = lane >> 2, cf = (lane & 3) << 1;
    const float base = exp2f((float)(n0 - m0) * LOG2G);
    __half* A = g_A + (size_t)b * L_ * L_;

#pragma unroll
    for (int i = 0; i < 2; ++i)
#pragma unroll
        for (int hf = 0; hf < 2; ++hf) {
            int r = wm0 + i * 16 + rf + hf * 8;
            int gn = n0 + r;
            float bp = base * pw[r];
#pragma unroll
            for (int j = 0; j < 8; ++j) {
                int c = wn0 + j * 8 + cf;
                int gm = m0 + c;
                float v0 = (gm <= gn) ? acc[i][j][hf * 2] * (bp * ipw[c]) : 0.f;
                float v1 = (gm + 1 <= gn) ? acc[i][j][hf * 2 + 1] * (bp * ipw[c + 1]) : 0.f;
                __half2 hv = __floats2half2_rn(v0, v1);
                *reinterpret_cast<__half2*>(A + (size_t)gn * L_ + gm) = hv;
            }
        }
}

// ----------------- out = A @ V, 64-row tiles (balanced waves) ----------------
__global__ __launch_bounds__(256) void av_mm(float* __restrict__ out) {
    extern __shared__ uint16_t dsm[];
    uint32_t smb = smem_u32(dsm);
    const int t = threadIdx.x;
    const int b = blockIdx.z;
    const int j0 = blockIdx.x << 7;                     // output features
    const int n0 = (31 - (int)blockIdx.y) << 6;         // 64-row tiles, heavy first
    const int start = (n0 > WIN) ? (n0 - WIN) : 0;      // 64-granular window start
    const int nch = (n0 + 64 - start) >> 6;             // 1..5 chunks

    float acc[2][4][4] = {};
    gemm_loop64(acc,
                g_A + ((size_t)b * L_ + n0) * L_ + start,
                g_T16 + (size_t)b * L_ * D_ + (size_t)j0 * L_ + start,
                L_, L_, nch, smb, t);

    const int lane = t & 31, w = t >> 5;
    const int wm0 = (w >> 2) << 5, wn0 = (w & 3) << 5;
    const int rf = lane >> 2, cf = (lane & 3) << 1;

#pragma unroll
    for (int i = 0; i < 2; ++i)
#pragma unroll
        for (int hf = 0; hf < 2; ++hf) {
            int row = n0 + wm0 + i * 16 + rf + hf * 8;
#pragma unroll
            for (int j = 0; j < 4; ++j) {
                int col = j0 + wn0 + j * 8 + cf;
                float2 v;
                v.x = acc[i][j][hf * 2];
                v.y = acc[i][j][hf * 2 + 1];
                *reinterpret_cast<float2*>(out + ((size_t)(b * L_ + row)) * D_ + col) = v;
            }
        }
}

// -----------------------------------------------------------------------------
extern "C" void kernel_launch(void* const* d_in, const int* in_sizes, int n_in,
                              void* d_out, int out_size) {
    const float* X = (const float*)d_in[0];
    const float* WQ = (const float*)d_in[1];
    const float* WK = (const float*)d_in[2];
    const float* WV = (const float*)d_in[3];
    float* out = (float*)d_out;

    cudaFuncSetAttribute(proj_mm, cudaFuncAttributeMaxDynamicSharedMemorySize, GEMM_SMEM);
    cudaFuncSetAttribute(qk_mm, cudaFuncAttributeMaxDynamicSharedMemorySize, GEMM_SMEM);
    cudaFuncSetAttribute(av_mm, cudaFuncAttributeMaxDynamicSharedMemorySize, AV_SMEM);

    prep_kernel<<<NX_BLK + XT_BLK + 3072, 256>>>(X, WQ, WK, WV);
    proj_mm<<<dim3(8, 64, 3), 256, GEMM_SMEM>>>();
    qk_mm<<<dim3(3, 16, B_), 256, GEMM_SMEM>>>();
    av_mm<<<dim3(8, 32, B_), 256, AV_SMEM>>>(out);
}

// round 17
// speedup vs baseline: 1.2535x; 1.2535x over previous
#include <cuda_runtime.h>
#include <cuda_fp16.h>
#include <stdint.h>
#include <math.h>

#define B_ 4
#define L_ 2048
#define D_ 1024
#define NBL (B_ * L_)
#define WIN 256                         // decay truncation window (γ^257 ≈ 2.9e-4 rel)

#define LOG2G  (-0.045803734f)          // log2(0.96875)
#define L2_1E4 (13.287712379549449f)    // log2(10000)

#define STG_BYTES 36864                 // 128-row stage: A(18432) + B(18432)
#define GEMM_SMEM (2 * STG_BYTES)       // 72 KB
#define AV_STG 27648                    // 64-row stage: A(9216) + B(18432)
#define AV_SMEM (2 * AV_STG)            // 54 KB

// ------------------- global scratch (allocation-free rule) -------------------
__device__ __align__(16) __half g_X16[NBL * D_];
__device__ __align__(16) __half g_W16[3][D_ * D_];        // transposed [n][k]
__device__ __align__(16) __half g_Q16[NBL * D_];
__device__ __align__(16) __half g_K16[NBL * D_];
__device__ __align__(16) __half g_T16[NBL * D_];          // V^T [d][l]
__device__ __align__(16) __half g_A[(size_t)B_ * L_ * L_];
__device__ __align__(16) float2 g_xtQ[(size_t)L_ * (D_ / 2)];  // cQ,sQ
__device__ __align__(16) float2 g_xtK[(size_t)L_ * (D_ / 2)];  // cK,sK

// ------------------------------- helpers -------------------------------------
__device__ __forceinline__ uint32_t smem_u32(const void* p) {
    uint32_t a;
    asm("{ .reg .u64 t; cvta.to.shared.u64 t, %1; cvt.u32.u64 %0, t; }"
        : "=r"(a) : "l"(p));
    return a;
}

__device__ __forceinline__ void ldm4(uint32_t* r, uint32_t a) {
    asm volatile("ldmatrix.sync.aligned.m8n8.x4.shared.b16 {%0,%1,%2,%3}, [%4];"
                 : "=r"(r[0]), "=r"(r[1]), "=r"(r[2]), "=r"(r[3]) : "r"(a));
}

__device__ __forceinline__ void mma_f16(float* c, const uint32_t* a, const uint32_t* b) {
    asm volatile(
        "mma.sync.aligned.m16n8k16.row.col.f32.f16.f16.f32 "
        "{%0,%1,%2,%3}, {%4,%5,%6,%7}, {%8,%9}, {%0,%1,%2,%3};"
        : "+f"(c[0]), "+f"(c[1]), "+f"(c[2]), "+f"(c[3])
        : "r"(a[0]), "r"(a[1]), "r"(a[2]), "r"(a[3]), "r"(b[0]), "r"(b[1]));
}

__device__ __forceinline__ void cp16(uint32_t dst, const void* src) {
    asm volatile("cp.async.cg.shared.global [%0], [%1], 16;" :: "r"(dst), "l"(src));
}
__device__ __forceinline__ void cp_commit() {
    asm volatile("cp.async.commit_group;" ::: "memory");
}
template <int N>
__device__ __forceinline__ void cp_wait() {
    asm volatile("cp.async.wait_group %0;" :: "n"(N) : "memory");
}

// async-copy ROWS x 64 cols (16-bit), gmem(stride ld) -> smem(stride 72)
template <int ROWS>
__device__ __forceinline__ void cpaR(uint32_t sb, const uint16_t* __restrict__ g,
                                     int ld, int t) {
#pragma unroll
    for (int it = 0; it < ROWS / 32; ++it) {
        int idx = t + it * 256;
        int r = idx >> 3, sg = (idx & 7) << 3;
        cp16(sb + (uint32_t)(r * 72 + sg) * 2, g + (size_t)r * ld + sg);
    }
}

// -- CTA 128x128 GEMM mainloop: fp16, K-chunk 64, 2-stage cp.async (R10 form) -
__device__ __forceinline__ void gemm_loop1(
    float acc[2][8][4],
    const __half* __restrict__ Ag, const __half* __restrict__ Bg,
    int lda, int ldb, int nch64, uint32_t smb, int t) {
    const int lane = t & 31, w = t >> 5;
    const int wm0 = (w >> 1) << 5;
    const int wn0 = (w & 1) << 6;

    const int arow = wm0 + (lane & 15);
    const int acol = (lane >> 4) << 3;
    const uint32_t aOff = (uint32_t)(arow * 72 + acol) * 2;
    const int brow = wn0 + ((lane >> 4) << 3) + (lane & 7);
    const int bcol = ((lane >> 3) & 1) << 3;
    const uint32_t bOff = 18432u + (uint32_t)(brow * 72 + bcol) * 2;

    const uint16_t* Au = (const uint16_t*)Ag;
    const uint16_t* Bu = (const uint16_t*)Bg;

    cpaR<128>(smb, Au, lda, t);
    cpaR<128>(smb + 18432, Bu, ldb, t);
    cp_commit();

    for (int ch = 0; ch < nch64; ++ch) {
        if (ch + 1 < nch64) {
            uint32_t ns = smb + ((ch + 1) & 1) * STG_BYTES;
            cpaR<128>(ns, Au + (ch + 1) * 64, lda, t);
            cpaR<128>(ns + 18432, Bu + (ch + 1) * 64, ldb, t);
            cp_commit();
            cp_wait<1>();
        } else {
            cp_wait<0>();
        }
        __syncthreads();

        const uint32_t sb = smb + (ch & 1) * STG_BYTES;
        const uint32_t aA = sb + aOff;
        const uint32_t bB = sb + bOff;

#pragma unroll
        for (int kk = 0; kk < 4; ++kk) {
            const uint32_t kb = kk * 32;
            uint32_t af[2][4], bf[8][2];
#pragma unroll
            for (int i = 0; i < 2; ++i)
                ldm4(af[i], aA + i * 16 * 144 + kb);
#pragma unroll
            for (int jp = 0; jp < 4; ++jp) {
                uint32_t tp[4];
                ldm4(tp, bB + jp * 16 * 144 + kb);
                bf[2 * jp][0] = tp[0];     bf[2 * jp][1] = tp[1];
                bf[2 * jp + 1][0] = tp[2]; bf[2 * jp + 1][1] = tp[3];
            }
#pragma unroll
            for (int i = 0; i < 2; ++i)
#pragma unroll
                for (int j = 0; j < 8; ++j)
                    mma_f16(acc[i][j], af[i], bf[j]);
        }
        __syncthreads();
    }
}

// ---- CTA 64x128 GEMM mainloop (av): warp layout 2x4, acc[2][4][4] ----------
__device__ __forceinline__ void gemm_loop64(
    float acc[2][4][4],
    const __half* __restrict__ Ag, const __half* __restrict__ Bg,
    int lda, int ldb, int nch64, uint32_t smb, int t) {
    const int lane = t & 31, w = t >> 5;
    const int wm0 = (w >> 2) << 5;   // 0,32
    const int wn0 = (w & 3) << 5;    // 0,32,64,96

    const int arow = wm0 + (lane & 15);
    const int acol = (lane >> 4) << 3;
    const uint32_t aOff = (uint32_t)(arow * 72 + acol) * 2;
    const int brow = wn0 + ((lane >> 4) << 3) + (lane & 7);
    const int bcol = ((lane >> 3) & 1) << 3;
    const uint32_t bOff = 9216u + (uint32_t)(brow * 72 + bcol) * 2;

    const uint16_t* Au = (const uint16_t*)Ag;
    const uint16_t* Bu = (const uint16_t*)Bg;

    cpaR<64>(smb, Au, lda, t);
    cpaR<128>(smb + 9216, Bu, ldb, t);
    cp_commit();

    for (int ch = 0; ch < nch64; ++ch) {
        if (ch + 1 < nch64) {
            uint32_t ns = smb + ((ch + 1) & 1) * AV_STG;
            cpaR<64>(ns, Au + (ch + 1) * 64, lda, t);
            cpaR<128>(ns + 9216, Bu + (ch + 1) * 64, ldb, t);
            cp_commit();
            cp_wait<1>();
        } else {
            cp_wait<0>();
        }
        __syncthreads();

        const uint32_t sb = smb + (ch & 1) * AV_STG;
        const uint32_t aA = sb + aOff;
        const uint32_t bB = sb + bOff;

#pragma unroll
        for (int kk = 0; kk < 4; ++kk) {
            const uint32_t kb = kk * 32;
            uint32_t af[2][4], bf[4][2];
#pragma unroll
            for (int i = 0; i < 2; ++i)
                ldm4(af[i], aA + i * 16 * 144 + kb);
#pragma unroll
            for (int jp = 0; jp < 2; ++jp) {
                uint32_t tp[4];
                ldm4(tp, bB + jp * 16 * 144 + kb);
                bf[2 * jp][0] = tp[0];     bf[2 * jp][1] = tp[1];
                bf[2 * jp + 1][0] = tp[2]; bf[2 * jp + 1][1] = tp[3];
            }
#pragma unroll
            for (int i = 0; i < 2; ++i)
#pragma unroll
                for (int j = 0; j < 4; ++j)
                    mma_f16(acc[i][j], af[i], bf[j]);
        }
        __syncthreads();
    }
}

// -------------- fused prep: cvt X + xt tables + W transpose ------------------
#define NX_BLK ((NBL * D_) / 1024)      // 8192
#define XT_BLK ((L_ * 512) / 256)       // 4096
__global__ __launch_bounds__(256) void prep_kernel(const float* __restrict__ X,
                                                   const float* __restrict__ WQ,
                                                   const float* __restrict__ WK,
                                                   const float* __restrict__ WV) {
    __shared__ float ts[32][33];
    int bx = blockIdx.x;
    if (bx < NX_BLK) {
        size_t i = ((size_t)bx * 256 + threadIdx.x) * 4;
        float4 v = *reinterpret_cast<const float4*>(X + i);
        __half2 a = __floats2half2_rn(v.x, v.y);
        __half2 b = __floats2half2_rn(v.z, v.w);
        uint2 o;
        o.x = *reinterpret_cast<uint32_t*>(&a);
        o.y = *reinterpret_cast<uint32_t*>(&b);
        *reinterpret_cast<uint2*>(g_X16 + i) = o;
    } else if (bx < NX_BLK + XT_BLK) {
        int idx = (bx - NX_BLK) * 256 + threadIdx.x;  // pos*512 + cp
        int pos = idx >> 9;
        int cp = idx & 511;
        float sv = (2.0f * cp + 409.6f) * (1.0f / 1433.6f);
        float sc = exp2f((float)pos * (1.0f / 512.0f) * log2f(sv));
        float invf = exp2f(-(float)cp * (L2_1E4 / 512.0f));
        float s, c;
        sincosf((float)pos * invf, &s, &c);
        g_xtQ[idx] = make_float2(c * sc, s * sc);
        g_xtK[idx] = make_float2(c / sc, s / sc);
    } else {
        // W transpose: 3 x 1024 blocks, each 32x32
        int idx = bx - NX_BLK - XT_BLK;
        int S = idx >> 10;
        int rem = idx & 1023;
        int n0 = (rem & 31) * 32, k0 = (rem >> 5) * 32;
        const float* W = (S == 0) ? WQ : (S == 1 ? WK : WV);
        int tx = threadIdx.x & 31, ty = threadIdx.x >> 5;
#pragma unroll
        for (int j = 0; j < 4; ++j)
            ts[ty + 8 * j][tx] = W[(size_t)(k0 + ty + 8 * j) * D_ + n0 + tx];
        __syncthreads();
#pragma unroll
        for (int j = 0; j < 4; ++j)
            g_W16[S][(size_t)(n0 + ty + 8 * j) * D_ + k0 + tx] =
                __float2half_rn(ts[tx][ty + 8 * j]);
    }
}

// --------------- fused projection GEMM: z = 0:Q, 1:K, 2:V(->V^T) -------------
__global__ __launch_bounds__(256) void proj_mm() {
    extern __shared__ uint16_t dsm[];
    uint32_t smb = smem_u32(dsm);
    float acc[2][8][4] = {};
    const int t = threadIdx.x;
    const int MODE = blockIdx.z;
    const int n0 = blockIdx.x << 7, m0 = blockIdx.y << 7;

    gemm_loop1(acc,
               g_X16 + (size_t)m0 * D_,
               g_W16[MODE] + (size_t)n0 * D_,
               D_, D_, D_ / 64, smb, t);

    const int lane = t & 31, w = t >> 5;
    const int wm0 = (w >> 1) << 5, wn0 = (w & 1) << 6;
    const int rf = lane >> 2, cf = (lane & 3) << 1;

    if (MODE == 2) {
        // ---- V: write transposed directly to g_T16[d][l] via smem staging ----
#pragma unroll
        for (int i = 0; i < 2; ++i)
#pragma unroll
            for (int hf = 0; hf < 2; ++hf) {
                int r = wm0 + i * 16 + rf + hf * 8;
#pragma unroll
                for (int j = 0; j < 8; ++j) {
                    int c = wn0 + j * 8 + cf;
                    dsm[(uint32_t)c * 136 + r] =
                        (uint16_t)__half_as_ushort(__float2half_rn(acc[i][j][hf * 2]));
                    dsm[(uint32_t)(c + 1) * 136 + r] =
                        (uint16_t)__half_as_ushort(__float2half_rn(acc[i][j][hf * 2 + 1]));
                }
            }
        __syncthreads();
        const int b = m0 >> 11;
        const int l0 = m0 & (L_ - 1);
        __half* T = g_T16 + (size_t)b * L_ * D_;
#pragma unroll
        for (int it = 0; it < 8; ++it) {
            int idx = t + it * 256;
            int c = idx >> 4;
            int sg = (idx & 15) << 3;
            float4 v = *reinterpret_cast<const float4*>(dsm + (uint32_t)c * 136 + sg);
            *reinterpret_cast<float4*>(T + (size_t)(n0 + c) * L_ + l0 + sg) = v;
        }
        return;
    }

    // ---- Q / K: xPos rotation epilogue ----
    __half* dst = (MODE == 0) ? g_Q16 : g_K16;
    const float2* xt = (MODE == 0) ? g_xtQ : g_xtK;
#pragma unroll
    for (int i = 0; i < 2; ++i)
#pragma unroll
        for (int hf = 0; hf < 2; ++hf) {
            int row = m0 + wm0 + i * 16 + rf + hf * 8;
            int pos = row & (L_ - 1);
#pragma unroll
            for (int j = 0; j < 8; ++j) {
                int col = n0 + wn0 + j * 8 + cf;
                float x0 = acc[i][j][hf * 2], x1 = acc[i][j][hf * 2 + 1];
                float2 tb = xt[(size_t)pos * 512 + (col >> 1)];
                float y0 = x0 * tb.x - x1 * tb.y;
                float y1 = x1 * tb.x + x0 * tb.y;
                __half2 hv = __floats2half2_rn(y0, y1);
                *reinterpret_cast<__half2*>(dst + (size_t)row * D_ + col) = hv;
            }
        }
}

// -------------------- A = (Q K^T) * decay, fp16 (window tiles only) ----------
__global__ __launch_bounds__(256) void qk_mm() {
    extern __shared__ uint16_t dsm[];
    uint32_t smb = smem_u32(dsm);
    __shared__ float pw[128], ipw[128];
    const int t = threadIdx.x;
    const int b = blockIdx.z;
    const int nt = blockIdx.y;                 // query tile
    const int mt = nt - 2 + (int)blockIdx.x;   // key tile within 256-window
    if (mt < 0) return;
    const int n0 = nt << 7, m0 = mt << 7;

    if (t < 128) {
        pw[t] = exp2f((float)t * LOG2G);
        ipw[t] = exp2f(-(float)t * LOG2G);
    }

    float acc[2][8][4] = {};
    gemm_loop1(acc,
               g_Q16 + (size_t)(b * L_ + n0) * D_,
               g_K16 + (size_t)(b * L_ + m0) * D_,
               D_, D_, D_ / 64, smb, t);

    const int lane = t & 31, w = t >> 5;
    const int wm0 = (w >> 1) << 5, wn0 = (w & 1) << 6;
    const int rf = lane >> 2, cf = (lane & 3) << 1;
    const float base = exp2f((float)(n0 - m0) * LOG2G);
    __half* A = g_A + (size_t)b * L_ * L_;

#pragma unroll
    for (int i = 0; i < 2; ++i)
#pragma unroll
        for (int hf = 0; hf < 2; ++hf) {
            int r = wm0 + i * 16 + rf + hf * 8;
            int gn = n0 + r;
            float bp = base * pw[r];
#pragma unroll
            for (int j = 0; j < 8; ++j) {
                int c = wn0 + j * 8 + cf;
                int gm = m0 + c;
                float v0 = (gm <= gn) ? acc[i][j][hf * 2] * (bp * ipw[c]) : 0.f;
                float v1 = (gm + 1 <= gn) ? acc[i][j][hf * 2 + 1] * (bp * ipw[c + 1]) : 0.f;
                __half2 hv = __floats2half2_rn(v0, v1);
                *reinterpret_cast<__half2*>(A + (size_t)gn * L_ + gm) = hv;
            }
        }
}

// ----------------- out = A @ V, 64-row tiles (balanced waves) ----------------
__global__ __launch_bounds__(256) void av_mm(float* __restrict__ out) {
    extern __shared__ uint16_t dsm[];
    uint32_t smb = smem_u32(dsm);
    const int t = threadIdx.x;
    const int b = blockIdx.z;
    const int j0 = blockIdx.x << 7;                     // output features
    const int n0 = (31 - (int)blockIdx.y) << 6;         // 64-row tiles, heavy first
    const int start = (n0 > WIN) ? (n0 - WIN) : 0;      // 64-granular window start
    const int nch = (n0 + 64 - start) >> 6;             // 1..5 chunks

    float acc[2][4][4] = {};
    gemm_loop64(acc,
                g_A + ((size_t)b * L_ + n0) * L_ + start,
                g_T16 + (size_t)b * L_ * D_ + (size_t)j0 * L_ + start,
                L_, L_, nch, smb, t);

    const int lane = t & 31, w = t >> 5;
    const int wm0 = (w >> 2) << 5, wn0 = (w & 3) << 5;
    const int rf = lane >> 2, cf = (lane & 3) << 1;

#pragma unroll
    for (int i = 0; i < 2; ++i)
#pragma unroll
        for (int hf = 0; hf < 2; ++hf) {
            int row = n0 + wm0 + i * 16 + rf + hf * 8;
#pragma unroll
            for (int j = 0; j < 4; ++j) {
                int col = j0 + wn0 + j * 8 + cf;
                float2 v;
                v.x = acc[i][j][hf * 2];
                v.y = acc[i][j][hf * 2 + 1];
                *reinterpret_cast<float2*>(out + ((size_t)(b * L_ + row)) * D_ + col) = v;
            }
        }
}

// -----------------------------------------------------------------------------
extern "C" void kernel_launch(void* const* d_in, const int* in_sizes, int n_in,
                              void* d_out, int out_size) {
    const float* X = (const float*)d_in[0];
    const float* WQ = (const float*)d_in[1];
    const float* WK = (const float*)d_in[2];
    const float* WV = (const float*)d_in[3];
    float* out = (float*)d_out;

    cudaFuncSetAttribute(proj_mm, cudaFuncAttributeMaxDynamicSharedMemorySize, GEMM_SMEM);
    cudaFuncSetAttribute(qk_mm, cudaFuncAttributeMaxDynamicSharedMemorySize, GEMM_SMEM);
    cudaFuncSetAttribute(av_mm, cudaFuncAttributeMaxDynamicSharedMemorySize, AV_SMEM);

    prep_kernel<<<NX_BLK + XT_BLK + 3072, 256>>>(X, WQ, WK, WV);
    proj_mm<<<dim3(8, 64, 3), 256, GEMM_SMEM>>>();
    qk_mm<<<dim3(3, 16, B_), 256, GEMM_SMEM>>>();
    av_mm<<<dim3(8, 32, B_), 256, AV_SMEM>>>(out);
}